// round 4
// baseline (speedup 1.0000x reference)
#include <cuda_runtime.h>
#include <cuda_bf16.h>
#include <math.h>

// ---------------------------------------------------------------------------
// MambaFormerBlock: B=2, L=1024, D=1024, DIN=2048, DTR=64, DS=16, H=16, HD=64
// R = B*L = 2048 rows. TF32 tensor-core GEMMs with cp.async 3-stage pipeline.
// All GEMM operands are pre-rounded to tf32 (rna) by their producers.
// ---------------------------------------------------------------------------

#define R_ROWS   2048
#define D_MODEL  1024
#define DIN      2048
#define DTR      64
#define DS       16
#define NHEAD    16
#define HDIM     64
#define LSEQ     1024
#define BATCH    2
#define XP_SPLIT 8
#define STAGES   3
#define LDT      20          // padded row len (floats): 20*qr+qc conflict-free
#define STG_F    (128 * LDT) // floats per stage per matrix = 2560
#define SMEM_BYTES (2 * STAGES * STG_F * 4)   // 61440

// Scratch (device globals; no allocation allowed)
__device__ float g_xnm  [R_ROWS * D_MODEL];
__device__ float g_xna  [R_ROWS * D_MODEL];
__device__ float g_xr   [R_ROWS * 2 * DIN];
__device__ float g_u    [R_ROWS * DIN];
__device__ float g_dbc  [R_ROWS * 96];
__device__ float g_xpart[XP_SPLIT * R_ROWS * 96];
__device__ float g_delta[R_ROWS * DIN];
__device__ float g_y    [R_ROWS * DIN];
__device__ float g_qkv  [R_ROWS * 1152];
__device__ float g_ao   [R_ROWS * D_MODEL];
__device__ float g_comb [R_ROWS * 2 * D_MODEL];
__device__ float g_fpre [R_ROWS * D_MODEL];

// tf32-rounded weight arena
#define W_INPROJ   0                         // 4096*1024
#define W_XPROJ    (W_INPROJ + 4096*1024)    // 96*2048
#define W_DTPROJ   (W_XPROJ + 96*2048)       // 2048*64
#define W_OUTPROJ  (W_DTPROJ + 2048*64)      // 1024*2048
#define W_QKV      (W_OUTPROJ + 1024*2048)   // 1152*1024
#define W_OATTN    (W_QKV + 1152*1024)       // 1024*1024
#define W_FUSE     (W_OATTN + 1024*1024)     // 1024*2048
#define W_TOTAL    (W_FUSE + 1024*2048)
__device__ float g_wtf[W_TOTAL];

__device__ __forceinline__ unsigned f2tf(float x) {
    unsigned u;
    asm("cvt.rna.tf32.f32 %0, %1;" : "=r"(u) : "f"(x));
    return u;
}
__device__ __forceinline__ float f2tf_f(float x) { return __uint_as_float(f2tf(x)); }

// round-to-tf32 copy (float4 granularity; n must be multiple of 4)
__global__ void __launch_bounds__(256) round_tf32_kernel(
    const float* __restrict__ src, float* __restrict__ dst, int n4)
{
    int i = blockIdx.x * 256 + threadIdx.x;
    if (i < n4) {
        float4 v = ((const float4*)src)[i];
        v.x = f2tf_f(v.x); v.y = f2tf_f(v.y); v.z = f2tf_f(v.z); v.w = f2tf_f(v.w);
        ((float4*)dst)[i] = v;
    }
}

// ---------------------------------------------------------------------------
// LayerNorm (optionally two (w,b) pairs sharing the same stats). rnd -> tf32.
// ---------------------------------------------------------------------------
__global__ void __launch_bounds__(256) ln_dual_kernel(
    const float* __restrict__ x,
    const float* __restrict__ w1, const float* __restrict__ b1, float* __restrict__ o1,
    const float* __restrict__ w2, const float* __restrict__ b2, float* __restrict__ o2,
    int rnd)
{
    const int Dm = D_MODEL;
    int row = blockIdx.x;
    const float* xp = x + (size_t)row * Dm;
    float s = 0.f, s2 = 0.f;
    for (int i = threadIdx.x; i < Dm; i += 256) { float v = xp[i]; s += v; s2 += v * v; }
    #pragma unroll
    for (int off = 16; off; off >>= 1) {
        s  += __shfl_xor_sync(0xffffffffu, s,  off);
        s2 += __shfl_xor_sync(0xffffffffu, s2, off);
    }
    __shared__ float rs[8], rs2[8];
    __shared__ float mean_s, inv_s;
    int w = threadIdx.x >> 5, l = threadIdx.x & 31;
    if (!l) { rs[w] = s; rs2[w] = s2; }
    __syncthreads();
    if (threadIdx.x == 0) {
        float a = 0.f, a2 = 0.f;
        #pragma unroll
        for (int i = 0; i < 8; i++) { a += rs[i]; a2 += rs2[i]; }
        float mean = a / Dm;
        float var  = a2 / Dm - mean * mean;
        mean_s = mean;
        inv_s  = rsqrtf(var + 1e-5f);
    }
    __syncthreads();
    float mean = mean_s, inv = inv_s;
    for (int i = threadIdx.x; i < Dm; i += 256) {
        float v = (xp[i] - mean) * inv;
        float a = v * w1[i] + b1[i];
        o1[(size_t)row * Dm + i] = rnd ? f2tf_f(a) : a;
        if (o2) {
            float c = v * w2[i] + b2[i];
            o2[(size_t)row * Dm + i] = rnd ? f2tf_f(c) : c;
        }
    }
}

// ---------------------------------------------------------------------------
// TF32 tensor-core GEMM, cp.async 3-stage. C = A[M,K] @ W[N,K]^T
// (+bias)(+softplus)(+resid)(+tf32-round). Inputs must be pre-rounded tf32.
// BM=128, BN=128, BK=16, 256 threads (8 warps, warp tile 64x32 of m16n8k8).
// ---------------------------------------------------------------------------
__device__ __forceinline__ void mma_tf32(float* d, const unsigned* a, const unsigned* b) {
    asm volatile(
        "mma.sync.aligned.m16n8k8.row.col.f32.tf32.tf32.f32 "
        "{%0,%1,%2,%3}, {%4,%5,%6,%7}, {%8,%9}, {%0,%1,%2,%3};"
        : "+f"(d[0]), "+f"(d[1]), "+f"(d[2]), "+f"(d[3])
        : "r"(a[0]), "r"(a[1]), "r"(a[2]), "r"(a[3]), "r"(b[0]), "r"(b[1]));
}

__device__ __forceinline__ void cpa16(unsigned dst, const void* src, int pred_sz) {
    asm volatile("cp.async.cg.shared.global [%0], [%1], 16, %2;"
                 :: "r"(dst), "l"(src), "r"(pred_sz));
}

__global__ void __launch_bounds__(256, 2) gemm_tf32_kernel(
    const float* __restrict__ A, int lda,
    const float* __restrict__ W, int ldw,
    int klen,
    const float* __restrict__ bias,
    const float* __restrict__ resid, int ldr,
    float* __restrict__ C, int ldc,
    int N, int act, int rnd)
{
    extern __shared__ float dsm[];
    float* As_ = dsm;                       // [STAGES][128][LDT]
    float* Bs_ = dsm + STAGES * STG_F;

    const int tid  = threadIdx.x;
    const int lane = tid & 31;
    const int wid  = tid >> 5;
    const int m0   = (wid & 1) * 64;
    const int n0   = (wid >> 1) * 32;
    const int qr   = lane >> 2;
    const int qc   = lane & 3;

    const int bm = blockIdx.y * 128;
    const int bn = blockIdx.x * 128;
    const int ks = blockIdx.z * klen;

    // cp.async mapping: 2 float4 per thread per matrix per stage
    const int ra = tid >> 2;             // 0..63
    const int ca = (tid & 3) << 2;       // 0,4,8,12
    const unsigned sa0 = (unsigned)__cvta_generic_to_shared(As_);
    const unsigned sb0 = (unsigned)__cvta_generic_to_shared(Bs_);
    const int wsz0 = (bn + ra)      < N ? 16 : 0;
    const int wsz1 = (bn + ra + 64) < N ? 16 : 0;
    const float* Ap0 = A + (size_t)(bm + ra) * lda + ks + ca;
    const float* Ap1 = Ap0 + (size_t)64 * lda;
    const float* Wp0 = W + (size_t)min(bn + ra, N - 1) * ldw + ks + ca;
    const float* Wp1 = W + (size_t)min(bn + ra + 64, N - 1) * ldw + ks + ca;

    const int nk = klen >> 4;

    float acc[4][4][4];
    #pragma unroll
    for (int i = 0; i < 4; i++)
        #pragma unroll
        for (int j = 0; j < 4; j++)
            #pragma unroll
            for (int r = 0; r < 4; r++) acc[i][j][r] = 0.f;

    // prologue: issue STAGES-1 tiles
    #pragma unroll
    for (int s = 0; s < STAGES - 1; s++) {
        if (s < nk) {
            int off = s * 16;
            unsigned da = sa0 + (unsigned)(s * STG_F + ra * LDT + ca) * 4;
            unsigned db = sb0 + (unsigned)(s * STG_F + ra * LDT + ca) * 4;
            cpa16(da, Ap0 + off, 16);
            cpa16(da + 64 * LDT * 4, Ap1 + off, 16);
            cpa16(db, Wp0 + off, wsz0);
            cpa16(db + 64 * LDT * 4, Wp1 + off, wsz1);
        }
        asm volatile("cp.async.commit_group;");
    }

    for (int kt = 0; kt < nk; kt++) {
        asm volatile("cp.async.wait_group %0;" :: "n"(STAGES - 2));
        __syncthreads();

        // issue tile kt+STAGES-1
        int nxt = kt + STAGES - 1;
        if (nxt < nk) {
            int buf = nxt % STAGES;
            int off = nxt * 16;
            unsigned da = sa0 + (unsigned)(buf * STG_F + ra * LDT + ca) * 4;
            unsigned db = sb0 + (unsigned)(buf * STG_F + ra * LDT + ca) * 4;
            cpa16(da, Ap0 + off, 16);
            cpa16(da + 64 * LDT * 4, Ap1 + off, 16);
            cpa16(db, Wp0 + off, wsz0);
            cpa16(db + 64 * LDT * 4, Wp1 + off, wsz1);
        }
        asm volatile("cp.async.commit_group;");

        // compute tile kt
        const float* Acur = As_ + (kt % STAGES) * STG_F;
        const float* Bcur = Bs_ + (kt % STAGES) * STG_F;
        #pragma unroll
        for (int kc = 0; kc < 16; kc += 8) {
            unsigned af[4][4], bf[4][2];
            #pragma unroll
            for (int mt = 0; mt < 4; mt++) {
                int r = m0 + mt * 16 + qr;
                af[mt][0] = __float_as_uint(Acur[r * LDT + kc + qc]);
                af[mt][1] = __float_as_uint(Acur[(r + 8) * LDT + kc + qc]);
                af[mt][2] = __float_as_uint(Acur[r * LDT + kc + qc + 4]);
                af[mt][3] = __float_as_uint(Acur[(r + 8) * LDT + kc + qc + 4]);
            }
            #pragma unroll
            for (int nt = 0; nt < 4; nt++) {
                int c = n0 + nt * 8 + qr;
                bf[nt][0] = __float_as_uint(Bcur[c * LDT + kc + qc]);
                bf[nt][1] = __float_as_uint(Bcur[c * LDT + kc + qc + 4]);
            }
            #pragma unroll
            for (int mt = 0; mt < 4; mt++)
                #pragma unroll
                for (int nt = 0; nt < 4; nt++)
                    mma_tf32(acc[mt][nt], af[mt], bf[nt]);
        }
        __syncthreads();
    }

    // epilogue
    #pragma unroll
    for (int mt = 0; mt < 4; mt++) {
        #pragma unroll
        for (int nt = 0; nt < 4; nt++) {
            int r = bm + m0 + mt * 16 + qr;
            int c = bn + n0 + nt * 8 + 2 * qc;
            #pragma unroll
            for (int half = 0; half < 2; half++) {
                int rr = r + half * 8;
                #pragma unroll
                for (int cc = 0; cc < 2; cc++) {
                    int gc = c + cc;
                    if (gc < N) {
                        float v = acc[mt][nt][half * 2 + cc];
                        if (bias)  v += bias[gc];
                        if (act)   v = (v > 20.f) ? v : log1pf(__expf(v));
                        if (resid) v += resid[(size_t)rr * ldr + gc];
                        if (rnd)   v = f2tf_f(v);
                        C[(size_t)rr * ldc + gc] = v;
                    }
                }
            }
        }
    }
}

// reduce split-K partials for x_proj (round to tf32: feeds dt_proj GEMM)
__global__ void __launch_bounds__(256) reduce_xp_kernel(
    const float* __restrict__ part, float* __restrict__ out)
{
    int i = blockIdx.x * 256 + threadIdx.x;
    const int total = R_ROWS * 96;
    if (i < total) {
        float s = 0.f;
        #pragma unroll
        for (int z = 0; z < XP_SPLIT; z++) s += part[(size_t)z * total + i];
        out[i] = f2tf_f(s);
    }
}

// ---------------------------------------------------------------------------
// Depthwise causal conv (width 4) along L + bias + SiLU. Output tf32-rounded.
// ---------------------------------------------------------------------------
__global__ void __launch_bounds__(256) conv_silu_kernel(
    const float* __restrict__ xr,
    const float* __restrict__ cw, const float* __restrict__ cb,
    float* __restrict__ u)
{
    int idx = blockIdx.x * 256 + threadIdx.x;
    int d = idx & (DIN - 1);
    int r = idx >> 11;
    int l = r & (LSEQ - 1);
    float acc = cb[d];
    const float* base = xr + (size_t)r * (2 * DIN) + d;
    #pragma unroll
    for (int k = 0; k < 4; k++) {
        int l2 = l - 3 + k;
        if (l2 >= 0) acc += cw[d * 4 + k] * base[(size_t)(l2 - l) * (2 * DIN)];
    }
    float sv = acc / (1.f + __expf(-acc));
    u[idx] = f2tf_f(sv);
}

// ---------------------------------------------------------------------------
// Selective scan. 16 lanes per (b,d) chain. Output tf32-rounded (feeds GEMM).
// ---------------------------------------------------------------------------
__global__ void __launch_bounds__(256) scan_kernel(
    const float* __restrict__ delta, const float* __restrict__ u,
    const float* __restrict__ dbc,   const float* __restrict__ xr,
    const float* __restrict__ A_log, const float* __restrict__ Dskip,
    float* __restrict__ y)
{
    int t = blockIdx.x * 256 + threadIdx.x;
    int chain = t >> 4;
    int n = t & 15;
    int b = chain >> 11;
    int d = chain & (DIN - 1);
    float An = -__expf(A_log[d * DS + n]);
    float Dv = Dskip[d];
    float h = 0.f;
    size_t rowbase = (size_t)b * LSEQ;
    for (int l = 0; l < LSEQ; l++) {
        size_t row = rowbase + l;
        float dv = delta[row * DIN + d];
        float uv = u[row * DIN + d];
        float Bn = dbc[row * 96 + DTR + n];
        float Cn = dbc[row * 96 + DTR + DS + n];
        h = __expf(dv * An) * h + dv * Bn * uv;
        float p = h * Cn;
        p += __shfl_xor_sync(0xffffffffu, p, 8, 16);
        p += __shfl_xor_sync(0xffffffffu, p, 4, 16);
        p += __shfl_xor_sync(0xffffffffu, p, 2, 16);
        p += __shfl_xor_sync(0xffffffffu, p, 1, 16);
        if (n == 0) {
            float res = xr[row * (2 * DIN) + DIN + d];
            float sres = res / (1.f + __expf(-res));
            y[row * DIN + d] = f2tf_f((p + uv * Dv) * sres);
        }
    }
}

// ---------------------------------------------------------------------------
// Causal MQA attention. Output tf32-rounded (feeds oattn GEMM).
// ---------------------------------------------------------------------------
__global__ void __launch_bounds__(128) attn_kernel(
    const float* __restrict__ qkv, float* __restrict__ out)
{
    __shared__ float ks[64 * 64];
    __shared__ float vs[64 * 64];
    int b = blockIdx.z, h = blockIdx.y;
    int ql = blockIdx.x * 128 + threadIdx.x;
    size_t qrow = ((size_t)b * LSEQ + ql) * 1152;
    float4 q4[16];
    #pragma unroll
    for (int i = 0; i < 16; i++) q4[i] = *(const float4*)(qkv + qrow + h * HDIM + i * 4);
    float4 o4[16];
    #pragma unroll
    for (int i = 0; i < 16; i++) o4[i] = make_float4(0.f, 0.f, 0.f, 0.f);
    float m = -1e30f, lsum = 0.f;
    int ntiles = blockIdx.x * 2 + 2;
    for (int tk = 0; tk < ntiles; tk++) {
        int s0 = tk * 64;
        __syncthreads();
        for (int i = threadIdx.x; i < 64 * 16; i += 128) {
            int s = i >> 4, jj = i & 15;
            const float* kr = qkv + ((size_t)b * LSEQ + s0 + s) * 1152;
            ((float4*)ks)[i] = *(const float4*)(kr + 1024 + jj * 4);
            ((float4*)vs)[i] = *(const float4*)(kr + 1088 + jj * 4);
        }
        __syncthreads();
        int kcount = ql - s0 + 1;
        if (kcount > 64) kcount = 64;
        for (int s = 0; s < kcount; s++) {
            const float4* kp = (const float4*)(ks + s * 64);
            float sc = 0.f;
            #pragma unroll
            for (int i = 0; i < 16; i++) {
                float4 kk = kp[i];
                sc += q4[i].x * kk.x; sc += q4[i].y * kk.y;
                sc += q4[i].z * kk.z; sc += q4[i].w * kk.w;
            }
            sc *= 0.125f;
            const float4* vp = (const float4*)(vs + s * 64);
            if (sc <= m) {
                float p = __expf(sc - m);
                lsum += p;
                #pragma unroll
                for (int i = 0; i < 16; i++) {
                    float4 vv = vp[i];
                    o4[i].x += p * vv.x; o4[i].y += p * vv.y;
                    o4[i].z += p * vv.z; o4[i].w += p * vv.w;
                }
            } else {
                float sc2 = __expf(m - sc);
                m = sc;
                lsum = lsum * sc2 + 1.f;
                #pragma unroll
                for (int i = 0; i < 16; i++) {
                    float4 vv = vp[i];
                    o4[i].x = o4[i].x * sc2 + vv.x; o4[i].y = o4[i].y * sc2 + vv.y;
                    o4[i].z = o4[i].z * sc2 + vv.z; o4[i].w = o4[i].w * sc2 + vv.w;
                }
            }
        }
    }
    float inv = 1.f / lsum;
    float* op = out + ((size_t)b * LSEQ + ql) * D_MODEL + h * HDIM;
    #pragma unroll
    for (int i = 0; i < 16; i++) {
        float4 vv;
        vv.x = f2tf_f(o4[i].x * inv); vv.y = f2tf_f(o4[i].y * inv);
        vv.z = f2tf_f(o4[i].z * inv); vv.w = f2tf_f(o4[i].w * inv);
        *(float4*)(op + i * 4) = vv;
    }
}

// ---------------------------------------------------------------------------
// Launch
// ---------------------------------------------------------------------------
extern "C" void kernel_launch(void* const* d_in, const int* in_sizes, int n_in,
                              void* d_out, int out_size)
{
    const float* x          = (const float*)d_in[0];
    const float* mnorm_w    = (const float*)d_in[1];
    const float* mnorm_b    = (const float*)d_in[2];
    const float* in_proj_w  = (const float*)d_in[3];
    const float* conv_w     = (const float*)d_in[4];
    const float* conv_b     = (const float*)d_in[5];
    const float* x_proj_w   = (const float*)d_in[6];
    const float* dt_proj_w  = (const float*)d_in[7];
    const float* dt_proj_b  = (const float*)d_in[8];
    const float* A_log      = (const float*)d_in[9];
    const float* D_skip     = (const float*)d_in[10];
    const float* out_proj_w = (const float*)d_in[11];
    const float* norm1_w    = (const float*)d_in[12];
    const float* norm1_b    = (const float*)d_in[13];
    const float* wqkv_w     = (const float*)d_in[14];
    const float* wqkv_b     = (const float*)d_in[15];
    const float* oattn_w    = (const float*)d_in[16];
    const float* oattn_b    = (const float*)d_in[17];
    const float* fuse_w     = (const float*)d_in[18];
    const float* fuse_b     = (const float*)d_in[19];
    const float* fln_w      = (const float*)d_in[20];
    const float* fln_b      = (const float*)d_in[21];
    float* out = (float*)d_out;

    static int smem_set = 0;
    if (!smem_set) {
        cudaFuncSetAttribute(gemm_tf32_kernel,
                             cudaFuncAttributeMaxDynamicSharedMemorySize, SMEM_BYTES);
        smem_set = 1;
    }

    float *xnm, *xna, *xr, *u, *dbc, *xpart, *delta, *y, *qkv, *ao, *comb, *fpre, *wtf;
    cudaGetSymbolAddress((void**)&xnm,   g_xnm);
    cudaGetSymbolAddress((void**)&xna,   g_xna);
    cudaGetSymbolAddress((void**)&xr,    g_xr);
    cudaGetSymbolAddress((void**)&u,     g_u);
    cudaGetSymbolAddress((void**)&dbc,   g_dbc);
    cudaGetSymbolAddress((void**)&xpart, g_xpart);
    cudaGetSymbolAddress((void**)&delta, g_delta);
    cudaGetSymbolAddress((void**)&y,     g_y);
    cudaGetSymbolAddress((void**)&qkv,   g_qkv);
    cudaGetSymbolAddress((void**)&ao,    g_ao);
    cudaGetSymbolAddress((void**)&comb,  g_comb);
    cudaGetSymbolAddress((void**)&fpre,  g_fpre);
    cudaGetSymbolAddress((void**)&wtf,   g_wtf);

    // 0. pre-round all GEMM weights to tf32
    #define RND(srcp, off, n) \
        round_tf32_kernel<<<((n)/4 + 255)/256, 256>>>(srcp, wtf + off, (n)/4)
    RND(in_proj_w,  W_INPROJ,  4096*1024);
    RND(x_proj_w,   W_XPROJ,   96*2048);
    RND(dt_proj_w,  W_DTPROJ,  2048*64);
    RND(out_proj_w, W_OUTPROJ, 1024*2048);
    RND(wqkv_w,     W_QKV,     1152*1024);
    RND(oattn_w,    W_OATTN,   1024*1024);
    RND(fuse_w,     W_FUSE,    1024*2048);
    #undef RND

    // 1. Both input LayerNorms (shared stats), tf32-rounded outputs
    ln_dual_kernel<<<R_ROWS, 256>>>(x, mnorm_w, mnorm_b, xnm, norm1_w, norm1_b, xna, 1);

    // 2. in_proj: xr = xnm @ in_proj_w^T   (2048 x 4096, K=1024)
    gemm_tf32_kernel<<<dim3(4096/128, R_ROWS/128, 1), 256, SMEM_BYTES>>>(
        xnm, D_MODEL, wtf + W_INPROJ, D_MODEL, D_MODEL,
        nullptr, nullptr, 0, xr, 2*DIN, 2*DIN, 0, 0);

    // 3. depthwise conv + SiLU -> u (tf32)
    conv_silu_kernel<<<(R_ROWS * DIN) / 256, 256>>>(xr, conv_w, conv_b, u);

    // 4. x_proj split-K: partials (2048 x 96, K=2048, 8 slices of 256)
    gemm_tf32_kernel<<<dim3(1, R_ROWS/128, XP_SPLIT), 256, SMEM_BYTES>>>(
        u, DIN, wtf + W_XPROJ, DIN, DIN/XP_SPLIT,
        nullptr, nullptr, 0, xpart, 96, 96, 0, 0);
    reduce_xp_kernel<<<(R_ROWS * 96 + 255) / 256, 256>>>(xpart, dbc);

    // 5. dt_proj + softplus: delta (2048 x 2048, K=64, lda=96)
    gemm_tf32_kernel<<<dim3(DIN/128, R_ROWS/128, 1), 256, SMEM_BYTES>>>(
        dbc, 96, wtf + W_DTPROJ, DTR, DTR,
        dt_proj_b, nullptr, 0, delta, DIN, DIN, 1, 0);

    // 6. selective scan (+ D_skip + silu(res) gate) -> y (tf32)
    scan_kernel<<<(BATCH * DIN * 16) / 256, 256>>>(delta, u, dbc, xr, A_log, D_skip, y);

    // 7. out_proj + residual x -> comb[:, :1024] (tf32: feeds fuse)
    gemm_tf32_kernel<<<dim3(D_MODEL/128, R_ROWS/128, 1), 256, SMEM_BYTES>>>(
        y, DIN, wtf + W_OUTPROJ, DIN, DIN,
        nullptr, x, D_MODEL, comb, 2*D_MODEL, D_MODEL, 0, 1);

    // 8. wqkv (+bias): qkv (2048 x 1152, K=1024)
    gemm_tf32_kernel<<<dim3(1152/128, R_ROWS/128, 1), 256, SMEM_BYTES>>>(
        xna, D_MODEL, wtf + W_QKV, D_MODEL, D_MODEL,
        wqkv_b, nullptr, 0, qkv, 1152, 1152, 0, 0);

    // 9. causal MQA attention -> ao (tf32)
    attn_kernel<<<dim3(LSEQ/128, NHEAD, BATCH), 128>>>(qkv, ao);

    // 10. oattn (+bias) + residual x -> comb[:, 1024:] (tf32: feeds fuse)
    gemm_tf32_kernel<<<dim3(D_MODEL/128, R_ROWS/128, 1), 256, SMEM_BYTES>>>(
        ao, D_MODEL, wtf + W_OATTN, D_MODEL, D_MODEL,
        oattn_b, x, D_MODEL, comb + D_MODEL, 2*D_MODEL, D_MODEL, 0, 1);

    // 11. fuse GEMM (+bias): fpre = comb @ fuse_w^T  (2048 x 1024, K=2048)
    gemm_tf32_kernel<<<dim3(D_MODEL/128, R_ROWS/128, 1), 256, SMEM_BYTES>>>(
        comb, 2*D_MODEL, wtf + W_FUSE, 2*D_MODEL, 2*D_MODEL,
        fuse_b, nullptr, 0, fpre, D_MODEL, D_MODEL, 0, 0);

    // 12. final LayerNorm -> out (no rounding)
    ln_dual_kernel<<<R_ROWS, 256>>>(fpre, fln_w, fln_b, out, nullptr, nullptr, nullptr, 0);
}